// round 10
// baseline (speedup 1.0000x reference)
#include <cuda_runtime.h>
#include <math.h>
#include <stdint.h>

// ---------------- problem constants ----------------
#define VOCAB     151936
#define BATCH     3
#define TOPK      3
#define BEAMS     3
#define HIST      64

#define F4_PER_B   37984                  // VOCAB/4
#define CHUNK_F4   256                    // float4 per topk chunk (1024 elems)
#define NCHUNK     149                    // ceil(37984/256)
#define TOPK_JOBS  (BATCH * NCHUNK)       // 447

// kv: per-(l,b) slab = 2^19 float4
#define KV_F4_PER_UNIT 2048               // 256 threads * 8 float4
#define KV_UNITS   21504                  // 44040192 / 2048
#define UNITS_PER_SLAB 256                // 2^19 / 2048

#define RP_F4_TOTAL 113952                // 3 * 37984
#define RP_UNITS    112
#define TOTAL_UNITS (KV_UNITS + RP_UNITS) // 21616

#define PGRID 592                         // 148 SMs * 4 blocks: co-resident

// NaN-safe finite sentinel (-inf breaks exp-merges: -inf - -inf = NaN)
#define NEG_BIG (-3.0e38f)

// output layout (flattened tuple, float32):
#define OFF_TOK   176160768u
#define OFF_SAVE  176160771u
#define OFF_RP    176160966u
#define OFF_PROB  176616774u
#define OFF_MAX   176616777u

// ---------------- device scratch ----------------
__device__ float g_pm[BATCH][NCHUNK];
__device__ float g_ps[BATCH][NCHUNK];
__device__ float g_pval[BATCH][NCHUNK][TOPK];
__device__ int   g_pidx[BATCH][NCHUNK][TOPK];
__device__ int   g_beam_index[BEAMS];
__device__ int   g_tokens[BEAMS];
__device__ int   g_cnt;       // topk partials done (reset each call by combine)
__device__ int   g_bar_cnt;   // barrier arrivals (reset each call by releaser)
__device__ int   g_sense;     // sense-reversing flag (alternates across calls)

// ---------------- helpers ----------------
struct Top3 { float v[3]; int i[3]; };

__device__ __forceinline__ void top3_init(Top3& t) {
#pragma unroll
    for (int k = 0; k < 3; k++) { t.v[k] = NEG_BIG; t.i[k] = 0x7fffffff; }
}

// JAX top_k: descending values, ties -> smaller index
__device__ __forceinline__ void top3_insert(Top3& t, float v, int idx) {
    if (v > t.v[0] || (v == t.v[0] && idx < t.i[0])) {
        t.v[2] = t.v[1]; t.i[2] = t.i[1];
        t.v[1] = t.v[0]; t.i[1] = t.i[0];
        t.v[0] = v;      t.i[0] = idx;
    } else if (v > t.v[1] || (v == t.v[1] && idx < t.i[1])) {
        t.v[2] = t.v[1]; t.i[2] = t.i[1];
        t.v[1] = v;      t.i[1] = idx;
    } else if (v > t.v[2] || (v == t.v[2] && idx < t.i[2])) {
        t.v[2] = v;      t.i[2] = idx;
    }
}

__device__ __forceinline__ void top3_butterfly(Top3& t, int maxoff) {
    for (int off = maxoff; off > 0; off >>= 1) {
        float ov0 = __shfl_xor_sync(0xffffffffu, t.v[0], off);
        float ov1 = __shfl_xor_sync(0xffffffffu, t.v[1], off);
        float ov2 = __shfl_xor_sync(0xffffffffu, t.v[2], off);
        int   oi0 = __shfl_xor_sync(0xffffffffu, t.i[0], off);
        int   oi1 = __shfl_xor_sync(0xffffffffu, t.i[1], off);
        int   oi2 = __shfl_xor_sync(0xffffffffu, t.i[2], off);
        top3_insert(t, ov0, oi0);
        top3_insert(t, ov1, oi1);
        top3_insert(t, ov2, oi2);
    }
}

__device__ __forceinline__ float warp_max(float m, int maxoff) {
    for (int off = maxoff; off > 0; off >>= 1)
        m = fmaxf(m, __shfl_xor_sync(0xffffffffu, m, off));
    return m;
}
__device__ __forceinline__ float warp_sum(float s, int maxoff) {
    for (int off = maxoff; off > 0; off >>= 1)
        s += __shfl_xor_sync(0xffffffffu, s, off);
    return s;
}

// ---------------- the single persistent kernel ----------------
__global__ void __launch_bounds__(256, 4) beam_all(
        const float4* __restrict__ kv4,
        const float*  __restrict__ logits,
        const int*    __restrict__ save_id,
        const float*  __restrict__ rp,
        const float*  __restrict__ prev_prob,
        const float*  __restrict__ pen,
        float* __restrict__ out)
{
    const int r    = blockIdx.x;
    const int tid  = threadIdx.x;
    const int warp = tid >> 5, lane = tid & 31;

    // read current barrier sense BEFORE any arrival can flip it
    const int old_sense = *((volatile int*)&g_sense);

    // ================= phase 1: topk partials (blocks 0..446) =================
    if (r < TOPK_JOBS) {
        const int b = r / NCHUNK;
        const int c = r % NCHUNK;
        const float4* lg4 = (const float4*)(logits + (size_t)b * VOCAB);
        const float4* rb4 = (const float4*)(rp     + (size_t)b * VOCAB);

        int  f4 = c * CHUNK_F4 + tid;
        bool ok = f4 < F4_PER_B;
        float4 lv, rv;
        if (ok) { lv = lg4[f4]; rv = rb4[f4]; }

        Top3 t; top3_init(t);
        float m_t = NEG_BIG;
        float x[4];
        if (ok) {
            x[0] = lv.x * rv.x; x[1] = lv.y * rv.y; x[2] = lv.z * rv.z; x[3] = lv.w * rv.w;
#pragma unroll
            for (int e = 0; e < 4; e++) m_t = fmaxf(m_t, x[e]);
#pragma unroll
            for (int e = 0; e < 4; e++) top3_insert(t, x[e], f4 * 4 + e);
        }

        float m_w = warp_max(m_t, 16);
        float s_t = 0.f;
        if (ok) {
            s_t = (__expf(x[0] - m_w) + __expf(x[2] - m_w))
                + (__expf(x[1] - m_w) + __expf(x[3] - m_w));
        }
        float s_w = warp_sum(s_t, 16);
        top3_butterfly(t, 16);

        __shared__ float sv[8][3]; __shared__ int si[8][3];
        __shared__ float smx[8];   __shared__ float ssm[8];
        if (lane == 0) {
#pragma unroll
            for (int k = 0; k < 3; k++) { sv[warp][k] = t.v[k]; si[warp][k] = t.i[k]; }
            smx[warp] = m_w; ssm[warp] = s_w;
        }
        __syncthreads();

        if (warp == 0) {
            float mm = (lane < 8) ? smx[lane] : NEG_BIG;
            float ss = (lane < 8) ? ssm[lane] : 0.f;
            Top3 f;
            if (lane < 8) {
#pragma unroll
                for (int k = 0; k < 3; k++) { f.v[k] = sv[lane][k]; f.i[k] = si[lane][k]; }
            } else top3_init(f);
            float m_b = warp_max(mm, 4);
            ss *= __expf(mm - m_b);
            ss = warp_sum(ss, 4);
            top3_butterfly(f, 4);
            if (lane == 0) {
                g_pm[b][c] = m_b; g_ps[b][c] = ss;
#pragma unroll
                for (int k = 0; k < 3; k++) { g_pval[b][c][k] = f.v[k]; g_pidx[b][c][k] = f.i[k]; }
            }
        }
        __syncthreads();

        // last topk block runs the combine
        __shared__ int s_old;
        if (tid == 0) { __threadfence(); s_old = atomicAdd(&g_cnt, 1); }
        __syncthreads();
        if (s_old == TOPK_JOBS - 1) {
            __threadfence();  // acquire other blocks' partials

            __shared__ float c_v[BATCH][3]; __shared__ int c_i[BATCH][3];
            __shared__ float c_lse[BATCH];
            __shared__ int s_beam[BEAMS], s_tok[BEAMS];

            if (warp < BATCH) {
                int bb = warp;
                float mc[5], sc[5]; int cnt = 0;
                Top3 tt; top3_init(tt);
                for (int c2 = lane; c2 < NCHUNK; c2 += 32) {
                    mc[cnt] = g_pm[bb][c2]; sc[cnt] = g_ps[bb][c2]; cnt++;
#pragma unroll
                    for (int k = 0; k < 3; k++) top3_insert(tt, g_pval[bb][c2][k], g_pidx[bb][c2][k]);
                }
                float m_l = NEG_BIG;
                for (int i = 0; i < cnt; i++) m_l = fmaxf(m_l, mc[i]);
                float s_l = 0.f;
                for (int i = 0; i < cnt; i++) s_l += sc[i] * __expf(mc[i] - m_l);
                float m_w2 = warp_max(m_l, 16);
                s_l *= __expf(m_l - m_w2);
                s_l = warp_sum(s_l, 16);
                top3_butterfly(tt, 16);
                if (lane == 0) {
                    c_lse[bb] = m_w2 + logf(s_l);
#pragma unroll
                    for (int k = 0; k < 3; k++) { c_v[bb][k] = tt.v[k]; c_i[bb][k] = tt.i[k]; }
                }
            }
            __syncthreads();

            if (tid == 0) {
                float cand[BATCH * TOPK];
                for (int bb = 0; bb < BATCH; bb++) {
                    float pp = prev_prob[bb];
                    for (int k = 0; k < TOPK; k++)
                        cand[bb * TOPK + k] = (c_v[bb][k] - c_lse[bb]) + pp;
                }
                Top3 beam; top3_init(beam);
                for (int j = 0; j < BATCH * TOPK; j++) top3_insert(beam, cand[j], j);
                for (int i = 0; i < BEAMS; i++) {
                    int fl = beam.i[i];
                    int bi = fl / TOPK;
                    int tk = c_i[bi][fl % TOPK];
                    s_beam[i] = bi; s_tok[i] = tk;
                    g_beam_index[i] = bi; g_tokens[i] = tk;
                    out[OFF_TOK  + i] = (float)tk;
                    out[OFF_PROB + i] = beam.v[i];
                }
                out[OFF_MAX] = (float)s_tok[0];
                g_cnt = 0;  // reset topk counter for next replay
            }
            __syncthreads();

            for (int i = tid; i < BEAMS * (HIST + 1); i += 256) {
                int rr = i / (HIST + 1), cc = i % (HIST + 1);
                float v = (cc < HIST) ? (float)save_id[s_beam[rr] * HIST + cc] : (float)s_tok[rr];
                out[OFF_SAVE + i] = v;
            }
        }
    }

    // ================= sense-reversing grid barrier (592 co-resident blocks) ==
    if (tid == 0) {
        __threadfence();  // release this block's phase-1 writes
        int ticket = atomicAdd(&g_bar_cnt, 1);
        if (ticket == PGRID - 1) {
            g_bar_cnt = 0;                  // safe: nobody reads it until next call
            __threadfence();
            atomicExch(&g_sense, old_sense ^ 1);   // release
        } else {
            volatile int* vs = &g_sense;
            while (*vs == old_sense) __nanosleep(64);
        }
    }
    __syncthreads();
    __threadfence();  // acquire beam_index / tokens

    const int bi0 = g_beam_index[0], bi1 = g_beam_index[1], bi2 = g_beam_index[2];

    // ================= phase 2: strided copy units ============================
    for (int u = r; u < TOTAL_UNITS; u += PGRID) {
        if (u < KV_UNITS) {
            // KV gather-copy unit: 2048 float4, 8 per thread, MLP=8
            // (l, inner, b) order: b-duplicates adjacent in unit space -> L2 dedup
            int l     = u / (3 * UNITS_PER_SLAB);
            int rem   = u - l * (3 * UNITS_PER_SLAB);
            int inner = rem / 3;
            int b     = rem - inner * 3;
            int bsel  = (b == 0) ? bi0 : ((b == 1) ? bi1 : bi2);
            int base  = ((l * 3 + b) << 19) + inner * KV_F4_PER_UNIT + tid;
            int delta = (bsel - b) << 19;
            float4 v[8];
#pragma unroll
            for (int k = 0; k < 8; k++) v[k] = kv4[base + k * 256 + delta];
            float4* dst = (float4*)out;
#pragma unroll
            for (int k = 0; k < 8; k++) __stcs(&dst[base + k * 256], v[k]);
        } else {
            // repeat_penality gather + token multiply
            int rb = u - KV_UNITS;
            const float4* rp4 = (const float4*)rp;
            float pv = pen[0];
#pragma unroll
            for (int k = 0; k < 4; k++) {
                int j = rb * 1024 + tid + k * 256;
                if (j < RP_F4_TOTAL) {
                    int b  = j / F4_PER_B;
                    int v4 = j - b * F4_PER_B;
                    int bsel = (b == 0) ? bi0 : ((b == 1) ? bi1 : bi2);
                    float4 x = rp4[(size_t)bsel * F4_PER_B + v4];
                    int d = g_tokens[b] - v4 * 4;
                    if ((unsigned)d < 4u) ((float*)&x)[d] *= pv;
                    float2* o2 = (float2*)(out + OFF_RP + (size_t)j * 4);
                    o2[0] = make_float2(x.x, x.y);
                    o2[1] = make_float2(x.z, x.w);
                }
            }
        }
    }
}

// ---------------- launch ----------------
extern "C" void kernel_launch(void* const* d_in, const int* in_sizes, int n_in,
                              void* d_out, int out_size) {
    const float* kv      = (const float*)d_in[0];
    const float* logits  = (const float*)d_in[1];
    const int*   save_id = (const int*)d_in[2];
    const float* rp      = (const float*)d_in[3];
    const float* prev    = (const float*)d_in[4];
    const float* pen     = (const float*)d_in[5];
    float* out = (float*)d_out;

    beam_all<<<PGRID, 256>>>((const float4*)kv, logits, save_id, rp, prev, pen, out);
}

// round 11
// speedup vs baseline: 1.1748x; 1.1748x over previous
#include <cuda_runtime.h>
#include <math.h>
#include <stdint.h>

// ---------------- problem constants ----------------
#define VOCAB     151936
#define BATCH     3
#define TOPK      3
#define BEAMS     3
#define HIST      64

#define F4_PER_B   37984                  // VOCAB/4
#define CHUNK_F4   512                    // float4 per chunk (2048 elems)
#define NCHUNK     75                     // ceil(37984/512); last chunk = 96 f4
#define TOPK_GRID  (BATCH * NCHUNK)       // 225 blocks

// kv: per-(l,b) slab = 2^19 float4
#define KV_F4_PER_BLOCK 2048              // 256 threads * 8 float4
#define KV_BLOCKS  21504                  // 44040192 / 2048
#define UNITS_PER_SLAB 256

#define RP_F4_TOTAL 113952                // 3 * 37984
#define RP_BLOCKS   112

// NaN-safe finite sentinel (-inf breaks the exp-merge: -inf - -inf = NaN)
#define NEG_BIG (-3.0e38f)

// output layout (flattened tuple, float32):
#define OFF_TOK   176160768u
#define OFF_SAVE  176160771u
#define OFF_RP    176160966u
#define OFF_PROB  176616774u
#define OFF_MAX   176616777u

// ---------------- device scratch ----------------
__device__ float g_pm[BATCH][NCHUNK];
__device__ float g_ps[BATCH][NCHUNK];
__device__ float g_pval[BATCH][NCHUNK][TOPK];
__device__ int   g_pidx[BATCH][NCHUNK][TOPK];
__device__ int   g_beam_index[BEAMS];
__device__ int   g_tokens[BEAMS];
__device__ int   g_cnt;

// ---------------- helpers ----------------
struct Top3 { float v[3]; int i[3]; };

__device__ __forceinline__ void top3_init(Top3& t) {
#pragma unroll
    for (int k = 0; k < 3; k++) { t.v[k] = NEG_BIG; t.i[k] = 0x7fffffff; }
}

// JAX top_k: descending values, ties -> smaller index
__device__ __forceinline__ void top3_insert(Top3& t, float v, int idx) {
    if (v > t.v[0] || (v == t.v[0] && idx < t.i[0])) {
        t.v[2] = t.v[1]; t.i[2] = t.i[1];
        t.v[1] = t.v[0]; t.i[1] = t.i[0];
        t.v[0] = v;      t.i[0] = idx;
    } else if (v > t.v[1] || (v == t.v[1] && idx < t.i[1])) {
        t.v[2] = t.v[1]; t.i[2] = t.i[1];
        t.v[1] = v;      t.i[1] = idx;
    } else if (v > t.v[2] || (v == t.v[2] && idx < t.i[2])) {
        t.v[2] = v;      t.i[2] = idx;
    }
}

__device__ __forceinline__ void butterfly_merge(float& m, float& s, Top3& t) {
#pragma unroll
    for (int off = 16; off > 0; off >>= 1) {
        float om  = __shfl_xor_sync(0xffffffffu, m,      off);
        float os  = __shfl_xor_sync(0xffffffffu, s,      off);
        float ov0 = __shfl_xor_sync(0xffffffffu, t.v[0], off);
        float ov1 = __shfl_xor_sync(0xffffffffu, t.v[1], off);
        float ov2 = __shfl_xor_sync(0xffffffffu, t.v[2], off);
        int   oi0 = __shfl_xor_sync(0xffffffffu, t.i[0], off);
        int   oi1 = __shfl_xor_sync(0xffffffffu, t.i[1], off);
        int   oi2 = __shfl_xor_sync(0xffffffffu, t.i[2], off);
        float nm = fmaxf(m, om);
        s = s * __expf(m - nm) + os * __expf(om - nm);
        m = nm;
        top3_insert(t, ov0, oi0);
        top3_insert(t, ov1, oi1);
        top3_insert(t, ov2, oi2);
    }
}

// ---------------- kernel 1: fused topk partials + last-block combine ----------------
__global__ void __launch_bounds__(256) topk_fused(const float* __restrict__ logits,
                                                  const float* __restrict__ rp,
                                                  const float* __restrict__ prev_prob,
                                                  const int*   __restrict__ save_id,
                                                  float* __restrict__ out) {
    const int tid = threadIdx.x;
    const int b   = blockIdx.x / NCHUNK;
    const int c   = blockIdx.x % NCHUNK;
    const int warp = tid >> 5, lane = tid & 31;

    const float4* lg4 = (const float4*)(logits + (size_t)b * VOCAB);
    const float4* rb4 = (const float4*)(rp     + (size_t)b * VOCAB);

    // ---- front-batched vector loads (no compute between LDGs; MLP=4) ----
    int  f4a = c * CHUNK_F4 + tid;
    int  f4b = f4a + 256;
    bool oka = f4a < F4_PER_B;
    bool okb = f4b < F4_PER_B;
    float4 la, ra, lb, rb;
    if (oka) { la = lg4[f4a]; ra = rb4[f4a]; }
    if (okb) { lb = lg4[f4b]; rb = rb4[f4b]; }

    // ---- pass 1: products, max, top3 ----
    Top3 t; top3_init(t);
    float m = NEG_BIG;
    float xa[4], xb[4];
    if (oka) {
        xa[0] = la.x * ra.x; xa[1] = la.y * ra.y; xa[2] = la.z * ra.z; xa[3] = la.w * ra.w;
#pragma unroll
        for (int e = 0; e < 4; e++) { m = fmaxf(m, xa[e]); }
#pragma unroll
        for (int e = 0; e < 4; e++) top3_insert(t, xa[e], f4a * 4 + e);
    }
    if (okb) {
        xb[0] = lb.x * rb.x; xb[1] = lb.y * rb.y; xb[2] = lb.z * rb.z; xb[3] = lb.w * rb.w;
#pragma unroll
        for (int e = 0; e < 4; e++) { m = fmaxf(m, xb[e]); }
#pragma unroll
        for (int e = 0; e < 4; e++) top3_insert(t, xb[e], f4b * 4 + e);
    }

    // ---- pass 2: exp-sum vs thread max ----
    float s0 = 0.f, s1 = 0.f;
    if (oka) {
        s0 += __expf(xa[0] - m); s1 += __expf(xa[1] - m);
        s0 += __expf(xa[2] - m); s1 += __expf(xa[3] - m);
    }
    if (okb) {
        s0 += __expf(xb[0] - m); s1 += __expf(xb[1] - m);
        s0 += __expf(xb[2] - m); s1 += __expf(xb[3] - m);
    }
    float s = s0 + s1;

    butterfly_merge(m, s, t);

    __shared__ float sv[8][3]; __shared__ int si[8][3];
    __shared__ float smx[8];   __shared__ float ssm[8];
    if (lane == 0) {
#pragma unroll
        for (int k = 0; k < 3; k++) { sv[warp][k] = t.v[k]; si[warp][k] = t.i[k]; }
        smx[warp] = m; ssm[warp] = s;
    }
    __syncthreads();

    if (warp == 0) {
        float mm = (lane < 8) ? smx[lane] : NEG_BIG;
        float ss = (lane < 8) ? ssm[lane] : 0.f;
        Top3 f;
        if (lane < 8) {
#pragma unroll
            for (int k = 0; k < 3; k++) { f.v[k] = sv[lane][k]; f.i[k] = si[lane][k]; }
        } else top3_init(f);
        butterfly_merge(mm, ss, f);
        if (lane == 0) {
            g_pm[b][c] = mm; g_ps[b][c] = ss;
#pragma unroll
            for (int k = 0; k < 3; k++) { g_pval[b][c][k] = f.v[k]; g_pidx[b][c][k] = f.i[k]; }
        }
    }
    __syncthreads();

    // ---- last block does the combine ----
    __shared__ int s_old;
    if (tid == 0) { __threadfence(); s_old = atomicAdd(&g_cnt, 1); }
    __syncthreads();
    if (s_old != TOPK_GRID - 1) return;
    __threadfence();  // acquire other blocks' partials

    __shared__ float c_v[BATCH][3]; __shared__ int c_i[BATCH][3];
    __shared__ float c_lse[BATCH];
    __shared__ int s_beam[BEAMS], s_tok[BEAMS];

    if (warp < BATCH) {
        int bb = warp;
        float mm = g_pm[bb][lane];
        float ss = g_ps[bb][lane];
        Top3 tt;
#pragma unroll
        for (int k = 0; k < 3; k++) { tt.v[k] = g_pval[bb][lane][k]; tt.i[k] = g_pidx[bb][lane][k]; }
        for (int c2 = lane + 32; c2 < NCHUNK; c2 += 32) {
            float pm = g_pm[bb][c2], ps = g_ps[bb][c2];
            float nm = fmaxf(mm, pm);
            ss = ss * __expf(mm - nm) + ps * __expf(pm - nm);
            mm = nm;
#pragma unroll
            for (int k = 0; k < 3; k++) top3_insert(tt, g_pval[bb][c2][k], g_pidx[bb][c2][k]);
        }
        butterfly_merge(mm, ss, tt);
        if (lane == 0) {
            c_lse[bb] = mm + logf(ss);
#pragma unroll
            for (int k = 0; k < 3; k++) { c_v[bb][k] = tt.v[k]; c_i[bb][k] = tt.i[k]; }
        }
    }
    __syncthreads();

    if (tid == 0) {
        float cand[BATCH * TOPK];
        for (int bb = 0; bb < BATCH; bb++) {
            float pp = prev_prob[bb];
            for (int k = 0; k < TOPK; k++)
                cand[bb * TOPK + k] = (c_v[bb][k] - c_lse[bb]) + pp;
        }
        Top3 beam; top3_init(beam);
        for (int j = 0; j < BATCH * TOPK; j++) top3_insert(beam, cand[j], j);
        for (int i = 0; i < BEAMS; i++) {
            int fl = beam.i[i];
            int bi = fl / TOPK;
            int tk = c_i[bi][fl % TOPK];
            s_beam[i] = bi; s_tok[i] = tk;
            g_beam_index[i] = bi; g_tokens[i] = tk;
            out[OFF_TOK  + i] = (float)tk;
            out[OFF_PROB + i] = beam.v[i];
        }
        out[OFF_MAX] = (float)s_tok[0];
        g_cnt = 0;  // reset for graph replay
    }
    __syncthreads();

    for (int i = tid; i < BEAMS * (HIST + 1); i += 256) {
        int rr = i / (HIST + 1), cc = i % (HIST + 1);
        float v = (cc < HIST) ? (float)save_id[s_beam[rr] * HIST + cc] : (float)s_tok[rr];
        out[OFF_SAVE + i] = v;
    }
}

// ---------------- kernel 2: rp gather (first blocks) + KV gather-copy ----------------
__global__ void __launch_bounds__(256) gather_kernel(const float4* __restrict__ kv4,
                                                     const float*  __restrict__ rp,
                                                     const float*  __restrict__ pen,
                                                     float* __restrict__ out) {
    int r   = blockIdx.x;
    int tid = threadIdx.x;

    if (r < RP_BLOCKS) {
        // ---------- repeat_penality gather + token multiply ----------
        const float4* rp4 = (const float4*)rp;
        float pv = pen[0];
#pragma unroll
        for (int k = 0; k < 4; k++) {
            int j = r * 1024 + tid + k * 256;       // float4 index into rp_out
            if (j < RP_F4_TOTAL) {
                int b  = j / F4_PER_B;
                int v4 = j - b * F4_PER_B;
                float4 x = rp4[(size_t)g_beam_index[b] * F4_PER_B + v4];
                int d = g_tokens[b] - v4 * 4;
                if ((unsigned)d < 4u) ((float*)&x)[d] *= pv;
                float2* o2 = (float2*)(out + OFF_RP + (size_t)j * 4);  // 8B-aligned dest
                o2[0] = make_float2(x.x, x.y);
                o2[1] = make_float2(x.z, x.w);
            }
        }
    } else {
        // ---------- KV gather-copy: 2048 float4 per block, MLP=8 ----------
        // unit order (l, inner, b): the 3 b-copies of the same src region are
        // adjacent blocks -> deterministic L2 read reuse when beams duplicate
        int u     = r - RP_BLOCKS;
        int l     = u / (3 * UNITS_PER_SLAB);
        int rem   = u - l * (3 * UNITS_PER_SLAB);
        int inner = rem / 3;
        int b     = rem - inner * 3;
        int base  = ((l * 3 + b) << 19) + inner * KV_F4_PER_BLOCK + tid;
        int delta = (g_beam_index[b] - b) << 19;
        float4 v[8];
#pragma unroll
        for (int k = 0; k < 8; k++) v[k] = kv4[base + k * 256 + delta];
        float4* dst = (float4*)out;
#pragma unroll
        for (int k = 0; k < 8; k++) __stcs(&dst[base + k * 256], v[k]);
    }
}

// ---------------- launch ----------------
extern "C" void kernel_launch(void* const* d_in, const int* in_sizes, int n_in,
                              void* d_out, int out_size) {
    const float* kv      = (const float*)d_in[0];
    const float* logits  = (const float*)d_in[1];
    const int*   save_id = (const int*)d_in[2];
    const float* rp      = (const float*)d_in[3];
    const float* prev    = (const float*)d_in[4];
    const float* pen     = (const float*)d_in[5];
    float* out = (float*)d_out;

    topk_fused   <<<TOPK_GRID, 256>>>(logits, rp, prev, save_id, out);
    gather_kernel<<<RP_BLOCKS + KV_BLOCKS, 256>>>((const float4*)kv, rp, pen, out);
}

// round 12
// speedup vs baseline: 1.1863x; 1.0099x over previous
#include <cuda_runtime.h>
#include <math.h>
#include <stdint.h>

// ---------------- problem constants ----------------
#define VOCAB     151936
#define BATCH     3
#define TOPK      3
#define BEAMS     3
#define HIST      64

#define F4_PER_B   37984                  // VOCAB/4
#define CHUNK_F4   512                    // float4 per chunk (2048 elems)
#define NCHUNK     75                     // ceil(37984/512); last chunk = 96 f4
#define TOPK_GRID  (BATCH * NCHUNK)       // 225 blocks

// kv: per-(l,b) slab = 2^19 float4
#define KV_F4_PER_BLOCK 1024              // 256 threads * 4 float4 (best measured)
#define KV_BLOCKS  43008                  // 44040192 / 1024
#define UNITS_PER_SLAB 512                // 2^19 / 1024

#define RP_F4_TOTAL 113952                // 3 * 37984
#define RP_BLOCKS   112

// NaN-safe finite sentinel (-inf breaks the exp-merge: -inf - -inf = NaN)
#define NEG_BIG (-3.0e38f)

// output layout (flattened tuple, float32):
#define OFF_TOK   176160768u
#define OFF_SAVE  176160771u
#define OFF_RP    176160966u
#define OFF_PROB  176616774u
#define OFF_MAX   176616777u

// ---------------- device scratch ----------------
__device__ float g_pm[BATCH][NCHUNK];
__device__ float g_ps[BATCH][NCHUNK];
__device__ float g_pval[BATCH][NCHUNK][TOPK];
__device__ int   g_pidx[BATCH][NCHUNK][TOPK];
__device__ int   g_beam_index[BEAMS];
__device__ int   g_tokens[BEAMS];
__device__ int   g_cnt;

// ---------------- helpers ----------------
struct Top3 { float v[3]; int i[3]; };

__device__ __forceinline__ void top3_init(Top3& t) {
#pragma unroll
    for (int k = 0; k < 3; k++) { t.v[k] = NEG_BIG; t.i[k] = 0x7fffffff; }
}

// JAX top_k: descending values, ties -> smaller index
__device__ __forceinline__ void top3_insert(Top3& t, float v, int idx) {
    if (v > t.v[0] || (v == t.v[0] && idx < t.i[0])) {
        t.v[2] = t.v[1]; t.i[2] = t.i[1];
        t.v[1] = t.v[0]; t.i[1] = t.i[0];
        t.v[0] = v;      t.i[0] = idx;
    } else if (v > t.v[1] || (v == t.v[1] && idx < t.i[1])) {
        t.v[2] = t.v[1]; t.i[2] = t.i[1];
        t.v[1] = v;      t.i[1] = idx;
    } else if (v > t.v[2] || (v == t.v[2] && idx < t.i[2])) {
        t.v[2] = v;      t.i[2] = idx;
    }
}

__device__ __forceinline__ void butterfly_merge(float& m, float& s, Top3& t) {
#pragma unroll
    for (int off = 16; off > 0; off >>= 1) {
        float om  = __shfl_xor_sync(0xffffffffu, m,      off);
        float os  = __shfl_xor_sync(0xffffffffu, s,      off);
        float ov0 = __shfl_xor_sync(0xffffffffu, t.v[0], off);
        float ov1 = __shfl_xor_sync(0xffffffffu, t.v[1], off);
        float ov2 = __shfl_xor_sync(0xffffffffu, t.v[2], off);
        int   oi0 = __shfl_xor_sync(0xffffffffu, t.i[0], off);
        int   oi1 = __shfl_xor_sync(0xffffffffu, t.i[1], off);
        int   oi2 = __shfl_xor_sync(0xffffffffu, t.i[2], off);
        float nm = fmaxf(m, om);
        s = s * __expf(m - nm) + os * __expf(om - nm);
        m = nm;
        top3_insert(t, ov0, oi0);
        top3_insert(t, ov1, oi1);
        top3_insert(t, ov2, oi2);
    }
}

// ---------------- kernel 1: fused topk partials + last-block combine ----------------
__global__ void __launch_bounds__(256) topk_fused(const float* __restrict__ logits,
                                                  const float* __restrict__ rp,
                                                  const float* __restrict__ prev_prob,
                                                  const int*   __restrict__ save_id,
                                                  float* __restrict__ out) {
    const int tid = threadIdx.x;
    const int b   = blockIdx.x / NCHUNK;
    const int c   = blockIdx.x % NCHUNK;
    const int warp = tid >> 5, lane = tid & 31;

    const float4* lg4 = (const float4*)(logits + (size_t)b * VOCAB);
    const float4* rb4 = (const float4*)(rp     + (size_t)b * VOCAB);

    // ---- front-batched vector loads (no compute between LDGs; MLP=4) ----
    int  f4a = c * CHUNK_F4 + tid;
    int  f4b = f4a + 256;
    bool oka = f4a < F4_PER_B;
    bool okb = f4b < F4_PER_B;
    float4 la, ra, lb, rb;
    if (oka) { la = lg4[f4a]; ra = rb4[f4a]; }
    if (okb) { lb = lg4[f4b]; rb = rb4[f4b]; }

    // ---- pass 1: products, max, top3 ----
    Top3 t; top3_init(t);
    float m = NEG_BIG;
    float xa[4], xb[4];
    if (oka) {
        xa[0] = la.x * ra.x; xa[1] = la.y * ra.y; xa[2] = la.z * ra.z; xa[3] = la.w * ra.w;
#pragma unroll
        for (int e = 0; e < 4; e++) { m = fmaxf(m, xa[e]); }
#pragma unroll
        for (int e = 0; e < 4; e++) top3_insert(t, xa[e], f4a * 4 + e);
    }
    if (okb) {
        xb[0] = lb.x * rb.x; xb[1] = lb.y * rb.y; xb[2] = lb.z * rb.z; xb[3] = lb.w * rb.w;
#pragma unroll
        for (int e = 0; e < 4; e++) { m = fmaxf(m, xb[e]); }
#pragma unroll
        for (int e = 0; e < 4; e++) top3_insert(t, xb[e], f4b * 4 + e);
    }

    // ---- pass 2: exp-sum vs thread max ----
    float s0 = 0.f, s1 = 0.f;
    if (oka) {
        s0 += __expf(xa[0] - m); s1 += __expf(xa[1] - m);
        s0 += __expf(xa[2] - m); s1 += __expf(xa[3] - m);
    }
    if (okb) {
        s0 += __expf(xb[0] - m); s1 += __expf(xb[1] - m);
        s0 += __expf(xb[2] - m); s1 += __expf(xb[3] - m);
    }
    float s = s0 + s1;

    butterfly_merge(m, s, t);

    __shared__ float sv[8][3]; __shared__ int si[8][3];
    __shared__ float smx[8];   __shared__ float ssm[8];
    if (lane == 0) {
#pragma unroll
        for (int k = 0; k < 3; k++) { sv[warp][k] = t.v[k]; si[warp][k] = t.i[k]; }
        smx[warp] = m; ssm[warp] = s;
    }
    __syncthreads();

    if (warp == 0) {
        float mm = (lane < 8) ? smx[lane] : NEG_BIG;
        float ss = (lane < 8) ? ssm[lane] : 0.f;
        Top3 f;
        if (lane < 8) {
#pragma unroll
            for (int k = 0; k < 3; k++) { f.v[k] = sv[lane][k]; f.i[k] = si[lane][k]; }
        } else top3_init(f);
        butterfly_merge(mm, ss, f);
        if (lane == 0) {
            g_pm[b][c] = mm; g_ps[b][c] = ss;
#pragma unroll
            for (int k = 0; k < 3; k++) { g_pval[b][c][k] = f.v[k]; g_pidx[b][c][k] = f.i[k]; }
        }
    }
    __syncthreads();

    // ---- last block does the combine ----
    __shared__ int s_old;
    if (tid == 0) { __threadfence(); s_old = atomicAdd(&g_cnt, 1); }
    __syncthreads();
    if (s_old != TOPK_GRID - 1) return;
    __threadfence();  // acquire other blocks' partials

    __shared__ float c_v[BATCH][3]; __shared__ int c_i[BATCH][3];
    __shared__ float c_lse[BATCH];
    __shared__ int s_beam[BEAMS], s_tok[BEAMS];

    if (warp < BATCH) {
        int bb = warp;
        float mm = g_pm[bb][lane];
        float ss = g_ps[bb][lane];
        Top3 tt;
#pragma unroll
        for (int k = 0; k < 3; k++) { tt.v[k] = g_pval[bb][lane][k]; tt.i[k] = g_pidx[bb][lane][k]; }
        for (int c2 = lane + 32; c2 < NCHUNK; c2 += 32) {
            float pm = g_pm[bb][c2], ps = g_ps[bb][c2];
            float nm = fmaxf(mm, pm);
            ss = ss * __expf(mm - nm) + ps * __expf(pm - nm);
            mm = nm;
#pragma unroll
            for (int k = 0; k < 3; k++) top3_insert(tt, g_pval[bb][c2][k], g_pidx[bb][c2][k]);
        }
        butterfly_merge(mm, ss, tt);
        if (lane == 0) {
            c_lse[bb] = mm + logf(ss);
#pragma unroll
            for (int k = 0; k < 3; k++) { c_v[bb][k] = tt.v[k]; c_i[bb][k] = tt.i[k]; }
        }
    }
    __syncthreads();

    if (tid == 0) {
        float cand[BATCH * TOPK];
        for (int bb = 0; bb < BATCH; bb++) {
            float pp = prev_prob[bb];
            for (int k = 0; k < TOPK; k++)
                cand[bb * TOPK + k] = (c_v[bb][k] - c_lse[bb]) + pp;
        }
        Top3 beam; top3_init(beam);
        for (int j = 0; j < BATCH * TOPK; j++) top3_insert(beam, cand[j], j);
        for (int i = 0; i < BEAMS; i++) {
            int fl = beam.i[i];
            int bi = fl / TOPK;
            int tk = c_i[bi][fl % TOPK];
            s_beam[i] = bi; s_tok[i] = tk;
            g_beam_index[i] = bi; g_tokens[i] = tk;
            out[OFF_TOK  + i] = (float)tk;
            out[OFF_PROB + i] = beam.v[i];
        }
        out[OFF_MAX] = (float)s_tok[0];
        g_cnt = 0;  // reset for graph replay
    }
    __syncthreads();

    for (int i = tid; i < BEAMS * (HIST + 1); i += 256) {
        int rr = i / (HIST + 1), cc = i % (HIST + 1);
        float v = (cc < HIST) ? (float)save_id[s_beam[rr] * HIST + cc] : (float)s_tok[rr];
        out[OFF_SAVE + i] = v;
    }
}

// ---------------- kernel 2: rp gather (first blocks) + KV gather-copy ----------------
__global__ void __launch_bounds__(256) gather_kernel(const float4* __restrict__ kv4,
                                                     const float*  __restrict__ rp,
                                                     const float*  __restrict__ pen,
                                                     float* __restrict__ out) {
    int r   = blockIdx.x;
    int tid = threadIdx.x;

    if (r < RP_BLOCKS) {
        // ---------- repeat_penality gather + token multiply ----------
        const float4* rp4 = (const float4*)rp;
        float pv = pen[0];
#pragma unroll
        for (int k = 0; k < 4; k++) {
            int j = r * 1024 + tid + k * 256;       // float4 index into rp_out
            if (j < RP_F4_TOTAL) {
                int b  = j / F4_PER_B;
                int v4 = j - b * F4_PER_B;
                float4 x = rp4[(size_t)g_beam_index[b] * F4_PER_B + v4];
                int d = g_tokens[b] - v4 * 4;
                if ((unsigned)d < 4u) ((float*)&x)[d] *= pv;
                float2* o2 = (float2*)(out + OFF_RP + (size_t)j * 4);  // 8B-aligned dest
                o2[0] = make_float2(x.x, x.y);
                o2[1] = make_float2(x.z, x.w);
            }
        }
    } else {
        // ---------- KV gather-copy: 1024 float4 per block, 4 per thread ----------
        // best-measured copy granularity (R1); (l, inner, b) adjacency keeps the
        // 3 b-copies of each src region in adjacent blocks -> L2 read dedup
        int u     = r - RP_BLOCKS;
        int l     = u / (3 * UNITS_PER_SLAB);
        int rem   = u - l * (3 * UNITS_PER_SLAB);
        int inner = rem / 3;
        int b     = rem - inner * 3;
        int base  = ((l * 3 + b) << 19) + inner * KV_F4_PER_BLOCK + tid;
        int delta = (g_beam_index[b] - b) << 19;
        float4 v[4];
#pragma unroll
        for (int k = 0; k < 4; k++) v[k] = kv4[base + k * 256 + delta];
        float4* dst = (float4*)out;
#pragma unroll
        for (int k = 0; k < 4; k++) __stcs(&dst[base + k * 256], v[k]);
    }
}

// ---------------- launch ----------------
extern "C" void kernel_launch(void* const* d_in, const int* in_sizes, int n_in,
                              void* d_out, int out_size) {
    const float* kv      = (const float*)d_in[0];
    const float* logits  = (const float*)d_in[1];
    const int*   save_id = (const int*)d_in[2];
    const float* rp      = (const float*)d_in[3];
    const float* prev    = (const float*)d_in[4];
    const float* pen     = (const float*)d_in[5];
    float* out = (float*)d_out;

    topk_fused   <<<TOPK_GRID, 256>>>(logits, rp, prev, save_id, out);
    gather_kernel<<<RP_BLOCKS + KV_BLOCKS, 256>>>((const float4*)kv, rp, pen, out);
}